// round 12
// baseline (speedup 1.0000x reference)
#include <cuda_runtime.h>
#include <cuda_bf16.h>
#include <cstdint>

// WaveletPreprocessing: level-1 orthonormal Haar wavedec2 + waverec2 is an
// exact identity -> pure 512 MiB HBM->HBM copy.
//
// Search history (best = R7 config, reproduced twice: 156.1 / 156.4 us,
// DRAM 85.7-85.9%, ~6.8 TB/s):
//   R2  __ldcs/__stcs 512Tx8:   164.4us   R3 persistent: 181.0us
//   R4  CE memcpy:              344.2us   R5 __stwt:     168.0us
//   R7  256Tx16 (regs=72):      156.1us   R8 128Tx32:    156.0us (neutral)
//   R9  interleaved phases:     158.0us
// R11: Blackwell-only 256-bit global accesses (ld/st.global.cs.v8.f32,
// LDG.E.256/STG.E.256) via inline PTX -- unreachable from C++ types.
// Same R7 structure (256T, 64 KiB tile, 8192 one-shot blocks); each thread
// does 8 x 32B instead of 16 x 16B. Probes request granularity at the
// LTS/DRAM scheduler: warp-step = 1024B contiguous, half the L1tex
// wavefronts per byte.

constexpr int UNROLL  = 8;     // 32B ops per thread
constexpr int THREADS = 256;
constexpr int TILE    = THREADS * UNROLL * 2;   // in float4 units: 4096 = 64 KiB

__device__ __forceinline__ void ldg256_cs(const float4* p, float4& a, float4& b)
{
    asm("ld.global.cs.v8.f32 {%0,%1,%2,%3,%4,%5,%6,%7}, [%8];"
        : "=f"(a.x), "=f"(a.y), "=f"(a.z), "=f"(a.w),
          "=f"(b.x), "=f"(b.y), "=f"(b.z), "=f"(b.w)
        : "l"(p));
}

__device__ __forceinline__ void stg256_cs(float4* p, const float4& a, const float4& b)
{
    asm volatile("st.global.cs.v8.f32 [%0], {%1,%2,%3,%4,%5,%6,%7,%8};"
                 :: "l"(p),
                    "f"(a.x), "f"(a.y), "f"(a.z), "f"(a.w),
                    "f"(b.x), "f"(b.y), "f"(b.z), "f"(b.w)
                 : "memory");
}

__global__ void __launch_bounds__(THREADS, 2)
haar_identity_copy_kernel(const float4* __restrict__ src,
                          float4* __restrict__ dst,
                          long long n_vec)
{
    // Each thread: 8 x 32B (= 2 float4) accesses, stride THREADS*2 float4
    // between steps; warp covers 1024B contiguous per step.
    long long base = (long long)blockIdx.x * TILE + threadIdx.x * 2;

    if (base + (long long)(UNROLL - 1) * (THREADS * 2) + 1 < n_vec) {
        float4 a[UNROLL], b[UNROLL];
#pragma unroll
        for (int k = 0; k < UNROLL; k++)
            ldg256_cs(&src[base + (long long)k * (THREADS * 2)], a[k], b[k]);
#pragma unroll
        for (int k = 0; k < UNROLL; k++)
            stg256_cs(&dst[base + (long long)k * (THREADS * 2)], a[k], b[k]);
    } else {
        // Tail tile (never taken for n_vec = 2^25, kept for shape-safety).
#pragma unroll
        for (int k = 0; k < UNROLL; k++) {
            long long idx = base + (long long)k * (THREADS * 2);
            if (idx + 1 < n_vec) {
                dst[idx]     = src[idx];
                dst[idx + 1] = src[idx + 1];
            } else if (idx < n_vec) {
                dst[idx] = src[idx];
            }
        }
    }
}

extern "C" void kernel_launch(void* const* d_in, const int* in_sizes, int n_in,
                              void* d_out, int out_size)
{
    const float* x = (const float*)d_in[0];
    float* out = (float*)d_out;

    long long n = (long long)in_sizes[0];   // 134,217,728 floats
    long long n_vec = n / 4;                // 33,554,432 float4 (exact)

    int blocks = (int)((n_vec + TILE - 1) / TILE);  // 8192 blocks

    haar_identity_copy_kernel<<<blocks, THREADS>>>(
        (const float4*)x, (float4*)out, n_vec);

    (void)n_in; (void)out_size;
}

// round 13
// speedup vs baseline: 1.0053x; 1.0053x over previous
#include <cuda_runtime.h>
#include <cuda_bf16.h>
#include <cstdint>

// WaveletPreprocessing: level-1 orthonormal Haar wavedec2 + waverec2 is an
// exact identity (perfect reconstruction, even dims, crop is a no-op) ->
// the task is a pure 512 MiB HBM->HBM copy (output bytes == input bytes:
// a copy is the information-theoretic optimum).
//
// FINAL kernel after 12-round search. Probe matrix:
//   R1  plain float4 grid-stride:        178.9us (DRAM 74.2%)
//   R2  __ldcs/__stcs, 512T x  8 f4:     164.4us (DRAM 84.3%)
//   R3  persistent grid:                 181.0us (lost cross-CTA overlap)
//   R4  copy-engine memcpyAsync:         344.2us (CE ~3.1 TB/s)
//   R5  __stwt write-through stores:     168.0us (loses LTS victim bursting)
//   R7  256T x 16 f4 (regs=72):          156.1us (DRAM 85.7%)  <- FINAL
//   R8  128T x 32 f4:                    156.0us (tied; depth saturated)
//   R9  interleaved ld/st phases:        158.0us (mix already blended)
//   R10 (= R7 rerun):                    156.4us (DRAM 85.9%, 6.81 TB/s)
//   R11 256-bit LDG/STG.E.256:           157.5us (sector-granular anyway)
// ~6.8 TB/s = ~85% of 8 TB/s spec is the measured 1:1-stream wall on this
// part (DRAM read/write turnaround bound; spec floor would be 134us).
// Wins: evict-first streaming on both sides (+10% DRAM), genuine 16-deep
// per-thread LDG.128 scoreboard window (+1.5% DRAM, regs=72 forces it).

constexpr int UNROLL  = 16;
constexpr int THREADS = 256;

__global__ void __launch_bounds__(THREADS, 2)
haar_identity_copy_kernel(const float4* __restrict__ src,
                          float4* __restrict__ dst,
                          long long n_vec)
{
    // One 64 KiB tile (THREADS*UNROLL float4) per block; one-shot grid of
    // 8192 blocks. Fresh blocks' front-batched loads overlap retiring
    // blocks' store drains across tile boundaries.
    long long base = (long long)blockIdx.x * (THREADS * UNROLL) + threadIdx.x;

    if (base + (long long)(UNROLL - 1) * THREADS < n_vec) {
        // 16 genuinely-outstanding coalesced evict-first LDG.128 per thread,
        // then 16 evict-first STG.128.
        float4 v[UNROLL];
#pragma unroll
        for (int k = 0; k < UNROLL; k++)
            v[k] = __ldcs(&src[base + (long long)k * THREADS]);
#pragma unroll
        for (int k = 0; k < UNROLL; k++)
            __stcs(&dst[base + (long long)k * THREADS], v[k]);
    } else {
        // Tail tile (never taken for n_vec = 2^25, kept for shape-safety).
#pragma unroll
        for (int k = 0; k < UNROLL; k++) {
            long long idx = base + (long long)k * THREADS;
            if (idx < n_vec) __stcs(&dst[idx], __ldcs(&src[idx]));
        }
    }
}

extern "C" void kernel_launch(void* const* d_in, const int* in_sizes, int n_in,
                              void* d_out, int out_size)
{
    const float* x = (const float*)d_in[0];
    float* out = (float*)d_out;

    long long n = (long long)in_sizes[0];   // 134,217,728 floats
    long long n_vec = n / 4;                // 33,554,432 float4 (exact)

    long long tile = (long long)THREADS * UNROLL;   // 4096 float4 / block
    int blocks = (int)((n_vec + tile - 1) / tile);  // 8192 blocks

    haar_identity_copy_kernel<<<blocks, THREADS>>>(
        (const float4*)x, (float4*)out, n_vec);

    (void)n_in; (void)out_size;
}